// round 12
// baseline (speedup 1.0000x reference)
#include <cuda_runtime.h>
#include <math.h>

#define B_    32
#define HB_   16   // half batch
#define INC_  10
#define LIN_  16384
#define CH_   20
#define NPOLY 12
#define MM_   6
#define NB_   4
// lengths: l0=16434 -> 16422,16410,16398,16386

#define BUFN 10520000  // >= 32*20*16434

__device__ float g_xa[BUFN];
__device__ float g_xb[BUFN];
__device__ float g_y1[BUFN];
__device__ float g_y2[BUFN];
__device__ float g_lg[BUFN];

typedef unsigned long long ull;

__device__ __forceinline__ ull pk2(float lo, float hi) {
    ull r; asm("mov.b64 %0, {%1, %2};" : "=l"(r) : "f"(lo), "f"(hi)); return r;
}
__device__ __forceinline__ void upk2(ull v, float& lo, float& hi) {
    asm("mov.b64 {%0, %1}, %2;" : "=f"(lo), "=f"(hi) : "l"(v));
}
__device__ __forceinline__ ull fma2(ull a, ull b, ull c) {
    ull d; asm("fma.rn.f32x2 %0, %1, %2, %3;" : "=l"(d) : "l"(a), "l"(b), "l"(c));
    return d;
}

// Branchless gelu: Abramowitz-Stegun 7.1.26 erf approx (|abs err| < 1.5e-7)
__device__ __forceinline__ float gelu_f(float x) {
    float z = 0.7071067811865476f * x;
    float s = fabsf(z);
    float t = __fdividef(1.0f, fmaf(0.3275911f, s, 1.0f));
    float p = fmaf(fmaf(fmaf(fmaf(1.061405429f, t, -1.453152027f),
                             t, 1.421413741f), t, -0.284496736f), t, 0.254829592f) * t;
    float e = __expf(-s * s);
    float er = fmaf(-p, e, 1.0f);
    er = copysignf(er, z);
    return 0.5f * x * (1.0f + er);
}

// ---------------------------------------------------------------------------
// Task descriptor. type: 0=convA(+gelu), 1=legmix, 2=convB, 3=recon
// nTotal = nPerB * nB (total real blocks for this task)
// ---------------------------------------------------------------------------
struct TD {
    int type;
    int nTotal;
    int nPerB;    // blocks per batch (recon: per (batch,channel))
    int bOff;     // batch offset (recon: pre-scaled by CH_)
    int nB;       // batches (recon: batches*CH_)
    int lin;
    int ll;
    int lo;
    const float* in;
    const float* w;
    const float* aux;
    const float* in2;
    float* out;
};
struct Tasks { TD t[4]; int n; };

#define TB_ 32

// ---------------------------------------------------------------------------
// Multi-stage kernel. INTERLEAVED dispatch: task = bx % n, local = bx / n.
// Consecutive blocks alternate tasks -> every wave is heterogeneous, so
// latency-bound task types co-reside and fill each other's issue slots.
// ---------------------------------------------------------------------------
__global__ void __launch_bounds__(128) k_multi(Tasks T)
{
    __shared__ union {
        float sw[CH_ * CH_ * 3];                                        // conv
        struct { float xs[CH_][TB_ * 6 + 6]; float fd2[MM_ * NPOLY];
                 float lm[CH_ * MM_ * MM_]; } leg;                      // legmix
        struct { float sfr[MM_ * NPOLY]; float sbuf[128 * 6]; } rc;     // recon
    } smu;

    int idx   = blockIdx.x % T.n;
    int local = blockIdx.x / T.n;
    if (local >= T.t[idx].nTotal) return;

    int type = T.t[idx].type;
    int nPerB = T.t[idx].nPerB;
    int b  = T.t[idx].bOff + local / nPerB;
    int tb = local % nPerB;
    int tid = threadIdx.x;

    if (type == 0 || type == 2) {
        // ------------- conv3 20->20 (VT=2, direct LDG); type0 adds gelu ----
        int lin = T.t[idx].lin;
        const float* x = T.t[idx].in;
        const float* w = T.t[idx].w;
        float* outp = T.t[idx].out;

        float* sw = smu.sw;
        for (int i = tid; i < CH_ * CH_ * 3; i += 128) sw[i] = w[i];
        __syncthreads();

        int lout = lin - 2;
        int t0 = (tb * 128 + tid) * 2;
        if (t0 >= lout) return;
        bool has2 = (t0 + 1 < lout);

        const float* xb = x + (size_t)b * CH_ * lin;
        float a0[CH_], a1[CH_];
#pragma unroll
        for (int co = 0; co < CH_; co++) { a0[co] = 0.f; a1[co] = 0.f; }

#pragma unroll
        for (int ci = 0; ci < CH_; ci++) {
            const float* xp = xb + ci * lin + t0;
            float v0 = xp[0], v1 = xp[1], v2 = xp[2];
            float v3 = has2 ? xp[3] : 0.f;
#pragma unroll
            for (int co = 0; co < CH_; co++) {
                const float* wp = sw + (co * CH_ + ci) * 3;
                float w0 = wp[0], w1 = wp[1], w2 = wp[2];
                a0[co] = fmaf(w0, v0, fmaf(w1, v1, fmaf(w2, v2, a0[co])));
                a1[co] = fmaf(w0, v1, fmaf(w1, v2, fmaf(w2, v3, a1[co])));
            }
        }
        float* ob = outp + (size_t)b * CH_ * lout;
        if (type == 0) {
#pragma unroll
            for (int co = 0; co < CH_; co++) {
                ob[co * lout + t0] = gelu_f(a0[co]);
                if (has2) ob[co * lout + t0 + 1] = gelu_f(a1[co]);
            }
        } else {
#pragma unroll
            for (int co = 0; co < CH_; co++) {
                ob[co * lout + t0] = a0[co];
                if (has2) ob[co * lout + t0 + 1] = a1[co];
            }
        }
    } else if (type == 1) {
        // ------------- legmix: decompose + block-diag mix ------------------
        int lin = T.t[idx].lin;
        int ll  = T.t[idx].ll;
        const float* x = T.t[idx].in;
        const float* lm_g = T.t[idx].w;
        const float* fd = T.t[idx].aux;
        float* Lg = T.t[idx].out;

        float (*xs)[TB_ * 6 + 6] = smu.leg.xs;
        float* fd2 = smu.leg.fd2;
        float* lm  = smu.leg.lm;

        int T0 = tb * TB_;
        for (int i = tid; i < MM_ * NPOLY; i += 128) fd2[i] = 0.5f * fd[i];
        for (int i = tid; i < CH_ * MM_ * MM_; i += 128) lm[i] = lm_g[i];
        for (int i = tid; i < CH_ * (TB_ * 6 + 6); i += 128) {
            int ci = i / (TB_ * 6 + 6);
            int j  = i % (TB_ * 6 + 6);
            int pos = 6 * T0 + j;
            xs[ci][j] = (pos < lin) ? x[((size_t)b * CH_ + ci) * lin + pos] : 0.f;
        }
        __syncthreads();

        int wq = tid >> 5, lane = tid & 31;
        int t = T0 + lane;
        if (t >= ll) return;

#pragma unroll
        for (int gg = 0; gg < 5; gg++) {
            int g = wq * 5 + gg;
            float v[MM_];
#pragma unroll
            for (int i = 0; i < MM_; i++) {
                int q  = 6 * g + i;
                int mi = q / CH_;
                int ci = q % CH_;
                float s = 0.f;
#pragma unroll
                for (int k = 0; k < NPOLY; k++)
                    s = fmaf(fd2[mi * NPOLY + k], xs[ci][6 * lane + k], s);
                v[i] = s;
            }
#pragma unroll
            for (int o = 0; o < MM_; o++) {
                float s = 0.f;
#pragma unroll
                for (int i = 0; i < MM_; i++)
                    s = fmaf(lm[(g * MM_ + o) * MM_ + i], v[i], s);
                int p  = 6 * g + o;
                int mo = p / CH_;
                int co = p % CH_;
                Lg[(((size_t)b * MM_ + mo) * CH_ + co) * ll + t] = s;
            }
        }
    } else {
        // ------------- recon: overlap-add + residual + gelu, VT=6 ----------
        int ll = T.t[idx].ll;
        int lo = T.t[idx].lo;
        const float* Lg = T.t[idx].in;
        const float* fr = T.t[idx].aux;
        const float* y2 = T.t[idx].in2;
        float* outp = T.t[idx].out;

        // b flattens (batch, channel): b = batch*CH_ + co
        int co = b % CH_;
        int bb = b / CH_;

        float* sfr = smu.rc.sfr;
        float* sbuf = smu.rc.sbuf;
        if (tid < MM_ * NPOLY) sfr[tid] = fr[tid];
        __syncthreads();

        int nu = lo / 6;
        int u = tb * 128 + tid;
        if (u < nu) {
            int t0 = u + 1;
            const float* Lo = Lg + (((size_t)bb * MM_) * CH_ + co) * ll;
            size_t mstride = (size_t)CH_ * ll;
            float rec[6];
#pragma unroll
            for (int e = 0; e < 6; e++) rec[e] = 0.f;
#pragma unroll
            for (int m = 0; m < MM_; m++) {
                float uc = Lo[m * mstride + t0];
                float up = Lo[m * mstride + t0 - 1];
#pragma unroll
                for (int e = 0; e < 6; e++) {
                    rec[e] = fmaf(uc, sfr[m * NPOLY + e],     rec[e]);
                    rec[e] = fmaf(up, sfr[m * NPOLY + e + 6], rec[e]);
                }
            }
#pragma unroll
            for (int e = 0; e < 6; e++) sbuf[6 * tid + e] = rec[e];
        }
        __syncthreads();

        size_t bc = (size_t)bb * CH_ + co;
        int Tbase = tb * 768;
        int liny2 = lo + 8;
        const float* y2r = y2 + bc * liny2;
        float* outr = outp + bc * lo;
#pragma unroll
        for (int e2 = 0; e2 < 6; e2++) {
            int idx2 = tid + 128 * e2;
            int t = Tbase + idx2;
            if (t < lo)
                outr[t] = gelu_f(sbuf[idx2] + y2r[t + 4]);
        }
    }
}

// ---------------------------------------------------------------------------
// First conv: input (B,10,16384) wrap-padded (25,27), conv3 -> (B,20,16434)
// ---------------------------------------------------------------------------
__global__ void __launch_bounds__(128) k_first(
    const float* __restrict__ in, const float* __restrict__ w,
    float* __restrict__ out, int lout)
{
    __shared__ float sw[CH_ * INC_ * 3];
    int tid = threadIdx.x;
    for (int i = tid; i < CH_ * INC_ * 3; i += blockDim.x) sw[i] = w[i];
    __syncthreads();

    int b = blockIdx.y;
    int t = blockIdx.x * blockDim.x + tid;
    if (t >= lout) return;

    int base = t - 25;
    int i0 = base;     if (i0 < 0) i0 += LIN_; else if (i0 >= LIN_) i0 -= LIN_;
    int i1 = base + 1; if (i1 < 0) i1 += LIN_; else if (i1 >= LIN_) i1 -= LIN_;
    int i2 = base + 2; if (i2 < 0) i2 += LIN_; else if (i2 >= LIN_) i2 -= LIN_;

    const float* inb = in + (size_t)b * INC_ * LIN_;
    float acc[CH_];
#pragma unroll
    for (int co = 0; co < CH_; co++) acc[co] = 0.f;
#pragma unroll
    for (int ci = 0; ci < INC_; ci++) {
        float v0 = inb[ci * LIN_ + i0];
        float v1 = inb[ci * LIN_ + i1];
        float v2 = inb[ci * LIN_ + i2];
#pragma unroll
        for (int co = 0; co < CH_; co++) {
            const float* wp = sw + (co * INC_ + ci) * 3;
            acc[co] = fmaf(wp[0], v0, fmaf(wp[1], v1, fmaf(wp[2], v2, acc[co])));
        }
    }
    float* ob = out + (size_t)b * CH_ * lout;
#pragma unroll
    for (int co = 0; co < CH_; co++) ob[co * lout + t] = acc[co];
}

// ---------------------------------------------------------------------------
// Final 20->128(gelu)->1 with f32x2, VT=4 (validated).
// ---------------------------------------------------------------------------
__global__ void __launch_bounds__(128) k_final_f2(
    const float* __restrict__ x, const float* __restrict__ w11,
    const float* __restrict__ w_out, float* __restrict__ out, int lin)
{
    __shared__ __align__(16) float2 swd[128 * CH_];
    __shared__ float so[128];
    int tid = threadIdx.x;
    for (int i = tid; i < 128 * CH_; i += 128) {
        float v = w11[i];
        swd[i] = make_float2(v, v);
    }
    if (tid < 128) so[tid] = w_out[tid];
    __syncthreads();

    int b = blockIdx.y;
    int t0 = (blockIdx.x * 128 + tid) * 4;
    if (t0 >= LIN_) return;

    const float* xb = x + (size_t)b * CH_ * lin + t0;
    ull xv01[CH_], xv23[CH_];
#pragma unroll
    for (int c = 0; c < CH_; c++) {
        const float* xp = xb + c * lin;
        xv01[c] = pk2(xp[0], xp[1]);
        xv23[c] = pk2(xp[2], xp[3]);
    }

    ull zero = pk2(0.f, 0.f);
    ull acc01 = zero, acc23 = zero;
#pragma unroll 2
    for (int o = 0; o < 128; o++) {
        ull h01 = zero, h23 = zero;
#pragma unroll
        for (int c = 0; c < CH_; c++) {
            ull wv = *(const ull*)&swd[o * CH_ + c];
            h01 = fma2(wv, xv01[c], h01);
            h23 = fma2(wv, xv23[c], h23);
        }
        float h0, h1, h2, h3;
        upk2(h01, h0, h1); upk2(h23, h2, h3);
        float ov = so[o];
        ull ov2 = pk2(ov, ov);
        acc01 = fma2(ov2, pk2(gelu_f(h0), gelu_f(h1)), acc01);
        acc23 = fma2(ov2, pk2(gelu_f(h2), gelu_f(h3)), acc23);
    }
    float r0, r1, r2, r3;
    upk2(acc01, r0, r1); upk2(acc23, r2, r3);
    float4* op = (float4*)&out[(size_t)b * LIN_ + t0];
    *op = make_float4(r0, r1, r2, r3);
}

// ---------------------------------------------------------------------------
// Host-side task builders and launcher
// ---------------------------------------------------------------------------
static inline TD mkTD() { TD d; d.type = -1; d.nTotal = 0; d.nPerB = 0;
    d.bOff = 0; d.nB = 0; d.lin = 0; d.ll = 0; d.lo = 0;
    d.in = 0; d.w = 0; d.aux = 0; d.in2 = 0; d.out = 0; return d; }

static void do_launch(TD* ts, int n) {
    Tasks T;
    int mx = 0;
    for (int i = 0; i < n; i++) {
        ts[i].nTotal = ts[i].nPerB * ts[i].nB;
        if (ts[i].nTotal > mx) mx = ts[i].nTotal;
        T.t[i] = ts[i];
    }
    T.n = n;
    k_multi<<<mx * n, 128>>>(T);
}

extern "C" void kernel_launch(void* const* d_in, const int* in_sizes, int n_in,
                              void* d_out, int out_size)
{
    const float* input  = (const float*)d_in[0];
    const float* w_first= (const float*)d_in[1];
    const float* conv_a = (const float*)d_in[2];
    const float* conv_b = (const float*)d_in[3];
    const float* lin_m  = (const float*)d_in[4];
    const float* w11    = (const float*)d_in[5];
    const float* w_out  = (const float*)d_in[6];
    const float* filt_d = (const float*)d_in[7];
    const float* filt_r = (const float*)d_in[8];
    float* out = (float*)d_out;

    float *xa, *xb, *y1, *y2, *Lg;
    cudaGetSymbolAddress((void**)&xa, g_xa);
    cudaGetSymbolAddress((void**)&xb, g_xb);
    cudaGetSymbolAddress((void**)&y1, g_y1);
    cudaGetSymbolAddress((void**)&y2, g_y2);
    cudaGetSymbolAddress((void**)&Lg, g_lg);

    // Per-iteration lengths and buffers
    int lA[NB_], llA[NB_], loA[NB_];
    float* curA[NB_ + 1];
    curA[0] = xa;
    {
        int l = 16434;
        for (int i = 0; i < NB_; i++) {
            lA[i] = l; llA[i] = l / 6 - 1; loA[i] = l - 12;
            curA[i + 1] = (i % 2 == 0) ? xb : xa;
            l -= 12;
        }
    }

    // task constructors
    auto FA = [&](int i, int h) {
        TD d = mkTD(); d.type = 0;
        d.nPerB = (lA[i] - 2 + 255) / 256; d.bOff = h * HB_; d.nB = HB_;
        d.lin = lA[i]; d.in = curA[i]; d.w = conv_a + i * 1200; d.out = y1;
        return d;
    };
    auto LM = [&](int i, int h) {
        TD d = mkTD(); d.type = 1;
        d.nPerB = (llA[i] + TB_ - 1) / TB_; d.bOff = h * HB_; d.nB = HB_;
        d.lin = lA[i]; d.ll = llA[i]; d.in = curA[i];
        d.w = lin_m + i * 720; d.aux = filt_d; d.out = Lg;
        return d;
    };
    auto CB = [&](int i, int h) {
        TD d = mkTD(); d.type = 2;
        int lin = lA[i] - 2;
        d.nPerB = (lin - 2 + 255) / 256; d.bOff = h * HB_; d.nB = HB_;
        d.lin = lin; d.in = y1; d.w = conv_b + i * 1200; d.out = y2;
        return d;
    };
    auto RC = [&](int i, int h) {
        TD d = mkTD(); d.type = 3;
        d.nPerB = (loA[i] / 6 + 127) / 128;
        d.bOff = h * HB_ * CH_; d.nB = HB_ * CH_;
        d.ll = llA[i]; d.lo = loA[i];
        d.in = Lg; d.aux = filt_r; d.in2 = y2; d.out = curA[i + 1];
        return d;
    };

    // First conv (full batch)
    {
        int l = 16434;
        dim3 g((l + 127) / 128, B_);
        k_first<<<g, 128>>>(input, w_first, xa, l);
    }

    TD ts[4];

    // L1: F(0,h0) + LM(0,h0)
    ts[0] = FA(0, 0); ts[1] = LM(0, 0); do_launch(ts, 2);
    for (int i = 0; i < NB_; i++) {
        // L: F(i,h1)+LM(i,h1) || C(i,h0)
        ts[0] = FA(i, 1); ts[1] = LM(i, 1); ts[2] = CB(i, 0); do_launch(ts, 3);
        // L: C(i,h1) || R(i,h0)
        ts[0] = CB(i, 1); ts[1] = RC(i, 0); do_launch(ts, 2);
        // L: R(i,h1) || F(i+1,h0)+LM(i+1,h0)
        if (i + 1 < NB_) {
            ts[0] = RC(i, 1); ts[1] = FA(i + 1, 0); ts[2] = LM(i + 1, 0);
            do_launch(ts, 3);
        } else {
            ts[0] = RC(i, 1); do_launch(ts, 1);
        }
    }

    // Final (full batch)
    dim3 gfin((LIN_ / 4 + 127) / 128, B_);
    k_final_f2<<<gfin, 128>>>(curA[NB_], w11, w_out, out, lA[NB_ - 1] - 12);
}

// round 13
// speedup vs baseline: 1.0957x; 1.0957x over previous
#include <cuda_runtime.h>
#include <math.h>

#define B_    32
#define INC_  10
#define LIN_  16384
#define CH_   20
#define NPOLY 12
#define MM_   6
#define NB_   4
// lengths: l0=16434 -> 16422,16410,16398,16386 (all divisible by 6)

#define BUFN 10520000  // >= 32*20*16434

__device__ float g_xa[BUFN];
__device__ float g_xb[BUFN];
__device__ float g_y1[BUFN];
__device__ float g_lg[BUFN];

typedef unsigned long long ull;

__device__ __forceinline__ ull pk2(float lo, float hi) {
    ull r; asm("mov.b64 %0, {%1, %2};" : "=l"(r) : "f"(lo), "f"(hi)); return r;
}
__device__ __forceinline__ void upk2(ull v, float& lo, float& hi) {
    asm("mov.b64 {%0, %1}, %2;" : "=f"(lo), "=f"(hi) : "l"(v));
}
__device__ __forceinline__ ull fma2(ull a, ull b, ull c) {
    ull d; asm("fma.rn.f32x2 %0, %1, %2, %3;" : "=l"(d) : "l"(a), "l"(b), "l"(c));
    return d;
}

// Branchless gelu: Abramowitz-Stegun 7.1.26 erf approx (|abs err| < 1.5e-7)
__device__ __forceinline__ float gelu_f(float x) {
    float z = 0.7071067811865476f * x;
    float s = fabsf(z);
    float t = __fdividef(1.0f, fmaf(0.3275911f, s, 1.0f));
    float p = fmaf(fmaf(fmaf(fmaf(1.061405429f, t, -1.453152027f),
                             t, 1.421413741f), t, -0.284496736f), t, 0.254829592f) * t;
    float e = __expf(-s * s);
    float er = fmaf(-p, e, 1.0f);
    er = copysignf(er, z);
    return 0.5f * x * (1.0f + er);
}

// ---------------------------------------------------------------------------
// First conv: input (B,10,16384) wrap-padded (25,27), conv3 -> (B,20,16434)
// ---------------------------------------------------------------------------
__global__ void __launch_bounds__(128) k_first(
    const float* __restrict__ in, const float* __restrict__ w,
    float* __restrict__ out, int lout)
{
    __shared__ float sw[CH_ * INC_ * 3];
    int tid = threadIdx.x;
    for (int i = tid; i < CH_ * INC_ * 3; i += blockDim.x) sw[i] = w[i];
    __syncthreads();

    int b = blockIdx.y;
    int t = blockIdx.x * blockDim.x + tid;
    if (t >= lout) return;

    int base = t - 25;
    int i0 = base;     if (i0 < 0) i0 += LIN_; else if (i0 >= LIN_) i0 -= LIN_;
    int i1 = base + 1; if (i1 < 0) i1 += LIN_; else if (i1 >= LIN_) i1 -= LIN_;
    int i2 = base + 2; if (i2 < 0) i2 += LIN_; else if (i2 >= LIN_) i2 -= LIN_;

    const float* inb = in + (size_t)b * INC_ * LIN_;
    float acc[CH_];
#pragma unroll
    for (int co = 0; co < CH_; co++) acc[co] = 0.f;
#pragma unroll
    for (int ci = 0; ci < INC_; ci++) {
        float v0 = inb[ci * LIN_ + i0];
        float v1 = inb[ci * LIN_ + i1];
        float v2 = inb[ci * LIN_ + i2];
#pragma unroll
        for (int co = 0; co < CH_; co++) {
            const float* wp = sw + (co * INC_ + ci) * 3;
            acc[co] = fmaf(wp[0], v0, fmaf(wp[1], v1, fmaf(wp[2], v2, acc[co])));
        }
    }
    float* ob = out + (size_t)b * CH_ * lout;
#pragma unroll
    for (int co = 0; co < CH_; co++) ob[co * lout + t] = acc[co];
}

// ---------------------------------------------------------------------------
// Fused launch (R9, validated): convA(+gelu) blocks ‖ legmix blocks, one grid.
// ---------------------------------------------------------------------------
#define TB_ 32
struct SmemConv { float sw[CH_ * CH_ * 3]; };
struct SmemLeg  { float xs[CH_][TB_ * 6 + 6]; float fd2[MM_ * NPOLY]; float lm[CH_ * MM_ * MM_]; };
union SmemU { SmemConv c; SmemLeg l; };

__global__ void __launch_bounds__(128) k_convA_legmix(
    const float* __restrict__ x, const float* __restrict__ wa,
    const float* __restrict__ lm_g, const float* __restrict__ fd,
    float* __restrict__ y1, float* __restrict__ Lg,
    int lin, int ll, int NA)
{
    __shared__ SmemU smu;
    int tid = threadIdx.x;
    int b = blockIdx.y;

    if ((int)blockIdx.x < NA) {
        // ---------------- conv_a path (VT=2, direct LDG, + gelu) ----------
        float* sw = smu.c.sw;
        for (int i = tid; i < CH_ * CH_ * 3; i += 128) sw[i] = wa[i];
        __syncthreads();

        int lout = lin - 2;
        int t0 = (blockIdx.x * 128 + tid) * 2;
        if (t0 >= lout) return;
        bool has2 = (t0 + 1 < lout);

        const float* xb = x + (size_t)b * CH_ * lin;
        float a0[CH_], a1[CH_];
#pragma unroll
        for (int co = 0; co < CH_; co++) { a0[co] = 0.f; a1[co] = 0.f; }

#pragma unroll
        for (int ci = 0; ci < CH_; ci++) {
            const float* xp = xb + ci * lin + t0;
            float v0 = xp[0], v1 = xp[1], v2 = xp[2];
            float v3 = has2 ? xp[3] : 0.f;
#pragma unroll
            for (int co = 0; co < CH_; co++) {
                const float* wp = sw + (co * CH_ + ci) * 3;
                float w0 = wp[0], w1 = wp[1], w2 = wp[2];
                a0[co] = fmaf(w0, v0, fmaf(w1, v1, fmaf(w2, v2, a0[co])));
                a1[co] = fmaf(w0, v1, fmaf(w1, v2, fmaf(w2, v3, a1[co])));
            }
        }
        float* ob = y1 + (size_t)b * CH_ * lout;
#pragma unroll
        for (int co = 0; co < CH_; co++) {
            ob[co * lout + t0] = gelu_f(a0[co]);
            if (has2) ob[co * lout + t0 + 1] = gelu_f(a1[co]);
        }
    } else {
        // ---------------- legmix path (4 warps x 5 groups, lane = tau) ----
        float (*xs)[TB_ * 6 + 6] = smu.l.xs;
        float* fd2 = smu.l.fd2;
        float* lm  = smu.l.lm;

        int T0 = (blockIdx.x - NA) * TB_;

        for (int i = tid; i < MM_ * NPOLY; i += 128) fd2[i] = 0.5f * fd[i];
        for (int i = tid; i < CH_ * MM_ * MM_; i += 128) lm[i] = lm_g[i];
        for (int i = tid; i < CH_ * (TB_ * 6 + 6); i += 128) {
            int ci = i / (TB_ * 6 + 6);
            int j  = i % (TB_ * 6 + 6);
            int pos = 6 * T0 + j;
            xs[ci][j] = (pos < lin) ? x[((size_t)b * CH_ + ci) * lin + pos] : 0.f;
        }
        __syncthreads();

        int wq = tid >> 5, lane = tid & 31;
        int t = T0 + lane;
        if (t >= ll) return;

#pragma unroll
        for (int gg = 0; gg < 5; gg++) {
            int g = wq * 5 + gg;
            float v[MM_];
#pragma unroll
            for (int i = 0; i < MM_; i++) {
                int q  = 6 * g + i;
                int mi = q / CH_;
                int ci = q % CH_;
                float s = 0.f;
#pragma unroll
                for (int k = 0; k < NPOLY; k++)
                    s = fmaf(fd2[mi * NPOLY + k], xs[ci][6 * lane + k], s);
                v[i] = s;
            }
#pragma unroll
            for (int o = 0; o < MM_; o++) {
                float s = 0.f;
#pragma unroll
                for (int i = 0; i < MM_; i++)
                    s = fmaf(lm[(g * MM_ + o) * MM_ + i], v[i], s);
                int p  = 6 * g + o;
                int mo = p / CH_;
                int co = p % CH_;
                Lg[(((size_t)b * MM_ + mo) * CH_ + co) * ll + t] = s;
            }
        }
    }
}

// ---------------------------------------------------------------------------
// NEW: fused convB + recon + residual + gelu per 252-output tile.
// Stage 1: convB (R2 pattern: VT=2, direct LDG from y1) -> y2 tile in smem.
//   Slot j holds y2 position T0+4+j; output t=T0+j needs y2[t+4] = slot j.
// Stage 2: recon groups of 6 sharing t0 (coalesced Lg loads across uu),
//   add residual in place, gelu.
// Stage 3: coalesced store.
// lo divisible by 6; tile NT=252 divisible by 6.
// ---------------------------------------------------------------------------
#define NT_ 252

__global__ void __launch_bounds__(128) k_cbrec(
    const float* __restrict__ y1, const float* __restrict__ wb,
    const float* __restrict__ Lg, const float* __restrict__ fr,
    float* __restrict__ out, int lo, int ll)
{
    __shared__ float sw[CH_ * CH_ * 3];     // 4800B
    __shared__ float sfr[MM_ * NPOLY];      // 288B
    __shared__ float y2s[CH_][NT_];         // 20160B

    int tid = threadIdx.x;
    int b = blockIdx.y;
    int T0 = blockIdx.x * NT_;

    for (int i = tid; i < CH_ * CH_ * 3; i += 128) sw[i] = wb[i];
    if (tid < MM_ * NPOLY) sfr[tid] = fr[tid];
    __syncthreads();

    int L1 = lo + 10;    // y1 row length
    int ly2 = lo + 8;    // y2 conceptual length

    // ---- Stage 1: convB into smem (126 threads active, VT=2) ----
    if (tid < NT_ / 2) {
        int p0 = T0 + 4 + 2 * tid;
        if (p0 < ly2) {
            bool has2 = (p0 + 1 < ly2);
            const float* yb = y1 + (size_t)b * CH_ * L1;
            float a0[CH_], a1[CH_];
#pragma unroll
            for (int co = 0; co < CH_; co++) { a0[co] = 0.f; a1[co] = 0.f; }
#pragma unroll
            for (int ci = 0; ci < CH_; ci++) {
                const float* xp = yb + ci * L1 + p0;
                float v0 = xp[0], v1 = xp[1], v2 = xp[2];
                float v3 = has2 ? xp[3] : 0.f;
#pragma unroll
                for (int co = 0; co < CH_; co++) {
                    const float* wp = sw + (co * CH_ + ci) * 3;
                    float w0 = wp[0], w1 = wp[1], w2 = wp[2];
                    a0[co] = fmaf(w0, v0, fmaf(w1, v1, fmaf(w2, v2, a0[co])));
                    a1[co] = fmaf(w0, v1, fmaf(w1, v2, fmaf(w2, v3, a1[co])));
                }
            }
            int j = 2 * tid;
#pragma unroll
            for (int co = 0; co < CH_; co++) {
                y2s[co][j] = a0[co];
                if (has2) y2s[co][j + 1] = a1[co];
            }
        }
    }
    __syncthreads();

    // ---- Stage 2: recon (shared-t0 groups of 6) + residual + gelu, in place
    int u0 = T0 / 6;
    int nu = lo / 6;
    size_t mstride = (size_t)CH_ * ll;
    for (int task = tid; task < CH_ * (NT_ / 6); task += 128) {
        int co = task / (NT_ / 6);
        int uu = task % (NT_ / 6);
        int u = u0 + uu;
        if (u >= nu) continue;
        int t0 = u + 1;
        const float* Lo = Lg + ((size_t)b * MM_ * CH_ + co) * ll;
        float rec[6];
#pragma unroll
        for (int e = 0; e < 6; e++) rec[e] = 0.f;
#pragma unroll
        for (int m = 0; m < MM_; m++) {
            float uc = Lo[m * mstride + t0];
            float up = Lo[m * mstride + t0 - 1];
#pragma unroll
            for (int e = 0; e < 6; e++) {
                rec[e] = fmaf(uc, sfr[m * NPOLY + e],     rec[e]);
                rec[e] = fmaf(up, sfr[m * NPOLY + e + 6], rec[e]);
            }
        }
        int jb = 6 * uu;
#pragma unroll
        for (int e = 0; e < 6; e++) {
            int t = T0 + jb + e;
            if (t < lo)
                y2s[co][jb + e] = gelu_f(rec[e] + y2s[co][jb + e]);
        }
    }
    __syncthreads();

    // ---- Stage 3: coalesced store ----
    float* ob = out + (size_t)b * CH_ * lo;
    for (int idx = tid; idx < CH_ * NT_; idx += 128) {
        int co = idx / NT_;
        int j  = idx % NT_;
        int t = T0 + j;
        if (t < lo) ob[co * lo + t] = y2s[co][j];
    }
}

// ---------------------------------------------------------------------------
// Final 20->128(gelu)->1 with f32x2, VT=4 (validated).
// ---------------------------------------------------------------------------
__global__ void __launch_bounds__(128) k_final_f2(
    const float* __restrict__ x, const float* __restrict__ w11,
    const float* __restrict__ w_out, float* __restrict__ out, int lin)
{
    __shared__ __align__(16) float2 swd[128 * CH_];
    __shared__ float so[128];
    int tid = threadIdx.x;
    for (int i = tid; i < 128 * CH_; i += 128) {
        float v = w11[i];
        swd[i] = make_float2(v, v);
    }
    if (tid < 128) so[tid] = w_out[tid];
    __syncthreads();

    int b = blockIdx.y;
    int t0 = (blockIdx.x * 128 + tid) * 4;
    if (t0 >= LIN_) return;

    const float* xb = x + (size_t)b * CH_ * lin + t0;
    ull xv01[CH_], xv23[CH_];
#pragma unroll
    for (int c = 0; c < CH_; c++) {
        const float* xp = xb + c * lin;
        xv01[c] = pk2(xp[0], xp[1]);
        xv23[c] = pk2(xp[2], xp[3]);
    }

    ull zero = pk2(0.f, 0.f);
    ull acc01 = zero, acc23 = zero;
#pragma unroll 2
    for (int o = 0; o < 128; o++) {
        ull h01 = zero, h23 = zero;
#pragma unroll
        for (int c = 0; c < CH_; c++) {
            ull wv = *(const ull*)&swd[o * CH_ + c];
            h01 = fma2(wv, xv01[c], h01);
            h23 = fma2(wv, xv23[c], h23);
        }
        float h0, h1, h2, h3;
        upk2(h01, h0, h1); upk2(h23, h2, h3);
        float ov = so[o];
        ull ov2 = pk2(ov, ov);
        acc01 = fma2(ov2, pk2(gelu_f(h0), gelu_f(h1)), acc01);
        acc23 = fma2(ov2, pk2(gelu_f(h2), gelu_f(h3)), acc23);
    }
    float r0, r1, r2, r3;
    upk2(acc01, r0, r1); upk2(acc23, r2, r3);
    float4* op = (float4*)&out[(size_t)b * LIN_ + t0];
    *op = make_float4(r0, r1, r2, r3);
}

// ---------------------------------------------------------------------------
extern "C" void kernel_launch(void* const* d_in, const int* in_sizes, int n_in,
                              void* d_out, int out_size)
{
    const float* input  = (const float*)d_in[0];
    const float* w_first= (const float*)d_in[1];
    const float* conv_a = (const float*)d_in[2];
    const float* conv_b = (const float*)d_in[3];
    const float* lin_m  = (const float*)d_in[4];
    const float* w11    = (const float*)d_in[5];
    const float* w_out  = (const float*)d_in[6];
    const float* filt_d = (const float*)d_in[7];
    const float* filt_r = (const float*)d_in[8];
    float* out = (float*)d_out;

    float *xa, *xb, *y1, *Lg;
    cudaGetSymbolAddress((void**)&xa, g_xa);
    cudaGetSymbolAddress((void**)&xb, g_xb);
    cudaGetSymbolAddress((void**)&y1, g_y1);
    cudaGetSymbolAddress((void**)&Lg, g_lg);

    int l = 16434;
    {
        dim3 g((l + 127) / 128, B_);
        k_first<<<g, 128>>>(input, w_first, xa, l);
    }

    float* cur = xa;
    float* alt = xb;
    for (int i = 0; i < NB_; i++) {
        int l1 = l - 2;
        int ll = l / 6 - 1;
        int lo = l - 12;

        int NA = (l1 + 255) / 256;      // conv_a blocks (VT=2, 128 thr)
        int NL = (ll + TB_ - 1) / TB_;  // legmix blocks
        dim3 gf(NA + NL, B_);
        k_convA_legmix<<<gf, 128>>>(cur, conv_a + i * CH_ * CH_ * 3,
                                    lin_m + i * CH_ * MM_ * MM_, filt_d,
                                    y1, Lg, l, ll, NA);

        dim3 gc((lo + NT_ - 1) / NT_, B_);
        k_cbrec<<<gc, 128>>>(y1, conv_b + i * CH_ * CH_ * 3,
                             Lg, filt_r, alt, lo, ll);

        float* tmp = cur; cur = alt; alt = tmp;
        l = lo;
    }

    dim3 gfin((LIN_ / 4 + 127) / 128, B_);
    k_final_f2<<<gfin, 128>>>(cur, w11, w_out, out, l);
}

// round 14
// speedup vs baseline: 1.4927x; 1.3624x over previous
#include <cuda_runtime.h>
#include <math.h>

#define B_    32
#define HB_   16   // half batch
#define INC_  10
#define LIN_  16384
#define CH_   20
#define NPOLY 12
#define MM_   6
#define NB_   4
// lengths: l0=16434 -> 16422,16410,16398,16386 (all divisible by 6)

#define BUFN 10520000  // >= 32*20*16434

__device__ float g_xa[BUFN];
__device__ float g_xb[BUFN];
__device__ float g_y1[BUFN];
__device__ float g_y2[BUFN];
__device__ float g_lg[BUFN];

typedef unsigned long long ull;

__device__ __forceinline__ ull pk2(float lo, float hi) {
    ull r; asm("mov.b64 %0, {%1, %2};" : "=l"(r) : "f"(lo), "f"(hi)); return r;
}
__device__ __forceinline__ void upk2(ull v, float& lo, float& hi) {
    asm("mov.b64 {%0, %1}, %2;" : "=f"(lo), "=f"(hi) : "l"(v));
}
__device__ __forceinline__ ull fma2(ull a, ull b, ull c) {
    ull d; asm("fma.rn.f32x2 %0, %1, %2, %3;" : "=l"(d) : "l"(a), "l"(b), "l"(c));
    return d;
}

// Branchless gelu: Abramowitz-Stegun 7.1.26 erf approx (|abs err| < 1.5e-7)
__device__ __forceinline__ float gelu_f(float x) {
    float z = 0.7071067811865476f * x;
    float s = fabsf(z);
    float t = __fdividef(1.0f, fmaf(0.3275911f, s, 1.0f));
    float p = fmaf(fmaf(fmaf(fmaf(1.061405429f, t, -1.453152027f),
                             t, 1.421413741f), t, -0.284496736f), t, 0.254829592f) * t;
    float e = __expf(-s * s);
    float er = fmaf(-p, e, 1.0f);
    er = copysignf(er, z);
    return 0.5f * x * (1.0f + er);
}

// ---------------------------------------------------------------------------
// First conv: input (B,10,16384) wrap-padded (25,27), conv3 -> (B,20,16434)
// Full batch.
// ---------------------------------------------------------------------------
__global__ void __launch_bounds__(128) k_first(
    const float* __restrict__ in, const float* __restrict__ w,
    float* __restrict__ out, int lout)
{
    __shared__ float sw[CH_ * INC_ * 3];
    int tid = threadIdx.x;
    for (int i = tid; i < CH_ * INC_ * 3; i += blockDim.x) sw[i] = w[i];
    __syncthreads();

    int b = blockIdx.y;
    int t = blockIdx.x * blockDim.x + tid;
    if (t >= lout) return;

    int base = t - 25;
    int i0 = base;     if (i0 < 0) i0 += LIN_; else if (i0 >= LIN_) i0 -= LIN_;
    int i1 = base + 1; if (i1 < 0) i1 += LIN_; else if (i1 >= LIN_) i1 -= LIN_;
    int i2 = base + 2; if (i2 < 0) i2 += LIN_; else if (i2 >= LIN_) i2 -= LIN_;

    const float* inb = in + (size_t)b * INC_ * LIN_;
    float acc[CH_];
#pragma unroll
    for (int co = 0; co < CH_; co++) acc[co] = 0.f;
#pragma unroll
    for (int ci = 0; ci < INC_; ci++) {
        float v0 = inb[ci * LIN_ + i0];
        float v1 = inb[ci * LIN_ + i1];
        float v2 = inb[ci * LIN_ + i2];
#pragma unroll
        for (int co = 0; co < CH_; co++) {
            const float* wp = sw + (co * INC_ + ci) * 3;
            acc[co] = fmaf(wp[0], v0, fmaf(wp[1], v1, fmaf(wp[2], v2, acc[co])));
        }
    }
    float* ob = out + (size_t)b * CH_ * lout;
#pragma unroll
    for (int co = 0; co < CH_; co++) ob[co * lout + t] = acc[co];
}

// ---------------------------------------------------------------------------
// Fused launch (R9, validated): convA(+gelu) blocks ‖ legmix blocks, one grid.
// b0 = batch offset (half-batch grids).
// ---------------------------------------------------------------------------
#define TB_ 32
struct SmemConv { float sw[CH_ * CH_ * 3]; };
struct SmemLeg  { float xs[CH_][TB_ * 6 + 6]; float fd2[MM_ * NPOLY]; float lm[CH_ * MM_ * MM_]; };
union SmemU { SmemConv c; SmemLeg l; };

__global__ void __launch_bounds__(128) k_convA_legmix(
    const float* __restrict__ x, const float* __restrict__ wa,
    const float* __restrict__ lm_g, const float* __restrict__ fd,
    float* __restrict__ y1, float* __restrict__ Lg,
    int lin, int ll, int NA, int b0)
{
    __shared__ SmemU smu;
    int tid = threadIdx.x;
    int b = b0 + blockIdx.y;

    if ((int)blockIdx.x < NA) {
        // ---------------- conv_a path (VT=2, direct LDG, + gelu) ----------
        float* sw = smu.c.sw;
        for (int i = tid; i < CH_ * CH_ * 3; i += 128) sw[i] = wa[i];
        __syncthreads();

        int lout = lin - 2;
        int t0 = (blockIdx.x * 128 + tid) * 2;
        if (t0 >= lout) return;
        bool has2 = (t0 + 1 < lout);

        const float* xb = x + (size_t)b * CH_ * lin;
        float a0[CH_], a1[CH_];
#pragma unroll
        for (int co = 0; co < CH_; co++) { a0[co] = 0.f; a1[co] = 0.f; }

#pragma unroll
        for (int ci = 0; ci < CH_; ci++) {
            const float* xp = xb + ci * lin + t0;
            float v0 = xp[0], v1 = xp[1], v2 = xp[2];
            float v3 = has2 ? xp[3] : 0.f;
#pragma unroll
            for (int co = 0; co < CH_; co++) {
                const float* wp = sw + (co * CH_ + ci) * 3;
                float w0 = wp[0], w1 = wp[1], w2 = wp[2];
                a0[co] = fmaf(w0, v0, fmaf(w1, v1, fmaf(w2, v2, a0[co])));
                a1[co] = fmaf(w0, v1, fmaf(w1, v2, fmaf(w2, v3, a1[co])));
            }
        }
        float* ob = y1 + (size_t)b * CH_ * lout;
#pragma unroll
        for (int co = 0; co < CH_; co++) {
            ob[co * lout + t0] = gelu_f(a0[co]);
            if (has2) ob[co * lout + t0 + 1] = gelu_f(a1[co]);
        }
    } else {
        // ---------------- legmix path (4 warps x 5 groups, lane = tau) ----
        float (*xs)[TB_ * 6 + 6] = smu.l.xs;
        float* fd2 = smu.l.fd2;
        float* lm  = smu.l.lm;

        int T0 = (blockIdx.x - NA) * TB_;

        for (int i = tid; i < MM_ * NPOLY; i += 128) fd2[i] = 0.5f * fd[i];
        for (int i = tid; i < CH_ * MM_ * MM_; i += 128) lm[i] = lm_g[i];
        for (int i = tid; i < CH_ * (TB_ * 6 + 6); i += 128) {
            int ci = i / (TB_ * 6 + 6);
            int j  = i % (TB_ * 6 + 6);
            int pos = 6 * T0 + j;
            xs[ci][j] = (pos < lin) ? x[((size_t)b * CH_ + ci) * lin + pos] : 0.f;
        }
        __syncthreads();

        int wq = tid >> 5, lane = tid & 31;
        int t = T0 + lane;
        if (t >= ll) return;

#pragma unroll
        for (int gg = 0; gg < 5; gg++) {
            int g = wq * 5 + gg;
            float v[MM_];
#pragma unroll
            for (int i = 0; i < MM_; i++) {
                int q  = 6 * g + i;
                int mi = q / CH_;
                int ci = q % CH_;
                float s = 0.f;
#pragma unroll
                for (int k = 0; k < NPOLY; k++)
                    s = fmaf(fd2[mi * NPOLY + k], xs[ci][6 * lane + k], s);
                v[i] = s;
            }
#pragma unroll
            for (int o = 0; o < MM_; o++) {
                float s = 0.f;
#pragma unroll
                for (int i = 0; i < MM_; i++)
                    s = fmaf(lm[(g * MM_ + o) * MM_ + i], v[i], s);
                int p  = 6 * g + o;
                int mo = p / CH_;
                int co = p % CH_;
                Lg[(((size_t)b * MM_ + mo) * CH_ + co) * ll + t] = s;
            }
        }
    }
}

// ---------------------------------------------------------------------------
// conv3 20->20, VALID, no gelu (R2/R9 version). b0 = batch offset.
// ---------------------------------------------------------------------------
__global__ void __launch_bounds__(128) k_conv20b(
    const float* __restrict__ x, const float* __restrict__ w,
    float* __restrict__ out, int lin, int b0)
{
    __shared__ float sw[CH_ * CH_ * 3];
    int tid = threadIdx.x;
    for (int i = tid; i < CH_ * CH_ * 3; i += blockDim.x) sw[i] = w[i];
    __syncthreads();

    int lout = lin - 2;
    int b = b0 + blockIdx.y;
    int t0 = (blockIdx.x * blockDim.x + tid) * 2;
    if (t0 >= lout) return;
    bool has2 = (t0 + 1 < lout);

    const float* xb = x + (size_t)b * CH_ * lin;
    float a0[CH_], a1[CH_];
#pragma unroll
    for (int co = 0; co < CH_; co++) { a0[co] = 0.f; a1[co] = 0.f; }

#pragma unroll
    for (int ci = 0; ci < CH_; ci++) {
        const float* xp = xb + ci * lin + t0;
        float v0 = xp[0], v1 = xp[1], v2 = xp[2];
        float v3 = has2 ? xp[3] : 0.f;
#pragma unroll
        for (int co = 0; co < CH_; co++) {
            const float* wp = sw + (co * CH_ + ci) * 3;
            float w0 = wp[0], w1 = wp[1], w2 = wp[2];
            a0[co] = fmaf(w0, v0, fmaf(w1, v1, fmaf(w2, v2, a0[co])));
            a1[co] = fmaf(w0, v1, fmaf(w1, v2, fmaf(w2, v3, a1[co])));
        }
    }
    float* ob = out + (size_t)b * CH_ * lout;
#pragma unroll
    for (int co = 0; co < CH_; co++) {
        ob[co * lout + t0] = a0[co];
        if (has2) ob[co * lout + t0 + 1] = a1[co];
    }
}

// ---------------------------------------------------------------------------
// Overlap-add reconstruction + residual + gelu, VT=6 (R9 version).
// b0 = batch offset; blockIdx.y spans HB_*CH_.
// ---------------------------------------------------------------------------
__global__ void __launch_bounds__(128) k_recon(
    const float* __restrict__ Lg, const float* __restrict__ fr,
    const float* __restrict__ y2, float* __restrict__ out,
    int ll, int lout, int b0)
{
    __shared__ float sfr[MM_ * NPOLY];
    __shared__ float sbuf[128 * 6];

    int tid = threadIdx.x;
    if (tid < MM_ * NPOLY) sfr[tid] = fr[tid];
    __syncthreads();

    int bc = b0 * CH_ + blockIdx.y;
    int b = bc / CH_, co = bc % CH_;
    int nu = lout / 6;

    int u = blockIdx.x * 128 + tid;
    if (u < nu) {
        int t0 = u + 1;
        const float* Lo = Lg + (((size_t)b * MM_) * CH_ + co) * ll;
        size_t mstride = (size_t)CH_ * ll;
        float rec[6];
#pragma unroll
        for (int e = 0; e < 6; e++) rec[e] = 0.f;
#pragma unroll
        for (int m = 0; m < MM_; m++) {
            float uc = Lo[m * mstride + t0];
            float up = Lo[m * mstride + t0 - 1];
#pragma unroll
            for (int e = 0; e < 6; e++) {
                rec[e] = fmaf(uc, sfr[m * NPOLY + e],     rec[e]);
                rec[e] = fmaf(up, sfr[m * NPOLY + e + 6], rec[e]);
            }
        }
#pragma unroll
        for (int e = 0; e < 6; e++) sbuf[6 * tid + e] = rec[e];
    }
    __syncthreads();

    int Tbase = blockIdx.x * 768;
    int liny2 = lout + 8;
    const float* y2r = y2 + (size_t)bc * liny2;
    float* outr = out + (size_t)bc * lout;
#pragma unroll
    for (int e2 = 0; e2 < 6; e2++) {
        int idx = tid + 128 * e2;
        int t = Tbase + idx;
        if (t < lout)
            outr[t] = gelu_f(sbuf[idx] + y2r[t + 4]);
    }
}

// ---------------------------------------------------------------------------
// Final 20->128(gelu)->1 with f32x2, VT=4 (validated). Full batch.
// ---------------------------------------------------------------------------
__global__ void __launch_bounds__(128) k_final_f2(
    const float* __restrict__ x, const float* __restrict__ w11,
    const float* __restrict__ w_out, float* __restrict__ out, int lin)
{
    __shared__ __align__(16) float2 swd[128 * CH_];
    __shared__ float so[128];
    int tid = threadIdx.x;
    for (int i = tid; i < 128 * CH_; i += 128) {
        float v = w11[i];
        swd[i] = make_float2(v, v);
    }
    if (tid < 128) so[tid] = w_out[tid];
    __syncthreads();

    int b = blockIdx.y;
    int t0 = (blockIdx.x * 128 + tid) * 4;
    if (t0 >= LIN_) return;

    const float* xb = x + (size_t)b * CH_ * lin + t0;
    ull xv01[CH_], xv23[CH_];
#pragma unroll
    for (int c = 0; c < CH_; c++) {
        const float* xp = xb + c * lin;
        xv01[c] = pk2(xp[0], xp[1]);
        xv23[c] = pk2(xp[2], xp[3]);
    }

    ull zero = pk2(0.f, 0.f);
    ull acc01 = zero, acc23 = zero;
#pragma unroll 2
    for (int o = 0; o < 128; o++) {
        ull h01 = zero, h23 = zero;
#pragma unroll
        for (int c = 0; c < CH_; c++) {
            ull wv = *(const ull*)&swd[o * CH_ + c];
            h01 = fma2(wv, xv01[c], h01);
            h23 = fma2(wv, xv23[c], h23);
        }
        float h0, h1, h2, h3;
        upk2(h01, h0, h1); upk2(h23, h2, h3);
        float ov = so[o];
        ull ov2 = pk2(ov, ov);
        acc01 = fma2(ov2, pk2(gelu_f(h0), gelu_f(h1)), acc01);
        acc23 = fma2(ov2, pk2(gelu_f(h2), gelu_f(h3)), acc23);
    }
    float r0, r1, r2, r3;
    upk2(acc01, r0, r1); upk2(acc23, r2, r3);
    float4* op = (float4*)&out[(size_t)b * LIN_ + t0];
    *op = make_float4(r0, r1, r2, r3);
}

// ---------------------------------------------------------------------------
extern "C" void kernel_launch(void* const* d_in, const int* in_sizes, int n_in,
                              void* d_out, int out_size)
{
    const float* input  = (const float*)d_in[0];
    const float* w_first= (const float*)d_in[1];
    const float* conv_a = (const float*)d_in[2];
    const float* conv_b = (const float*)d_in[3];
    const float* lin_m  = (const float*)d_in[4];
    const float* w11    = (const float*)d_in[5];
    const float* w_out  = (const float*)d_in[6];
    const float* filt_d = (const float*)d_in[7];
    const float* filt_r = (const float*)d_in[8];
    float* out = (float*)d_out;

    float *xa, *xb, *y1, *y2, *Lg;
    cudaGetSymbolAddress((void**)&xa, g_xa);
    cudaGetSymbolAddress((void**)&xb, g_xb);
    cudaGetSymbolAddress((void**)&y1, g_y1);
    cudaGetSymbolAddress((void**)&y2, g_y2);
    cudaGetSymbolAddress((void**)&Lg, g_lg);

    // Per-iteration lengths and ping-pong buffers
    int lA[NB_], llA[NB_], loA[NB_];
    float* curA[NB_ + 1];
    curA[0] = xa;
    {
        int l = 16434;
        for (int i = 0; i < NB_; i++) {
            lA[i] = l; llA[i] = l / 6 - 1; loA[i] = l - 12;
            curA[i + 1] = (i % 2 == 0) ? xb : xa;
            l -= 12;
        }
    }

    // Fork-join resources (created per call; kernel_launch only runs during
    // correctness + capture, never on graph replay, so no per-replay cost).
    cudaStream_t s1;
    cudaStreamCreateWithFlags(&s1, cudaStreamNonBlocking);
    cudaEvent_t evA[NB_], evJ;
    for (int i = 0; i < NB_; i++)
        cudaEventCreateWithFlags(&evA[i], cudaEventDisableTiming);
    cudaEventCreateWithFlags(&evJ, cudaEventDisableTiming);

    auto launchF = [&](int i, int h, cudaStream_t s) {
        int NA = (lA[i] - 2 + 255) / 256;
        int NL = (llA[i] + TB_ - 1) / TB_;
        dim3 g(NA + NL, HB_);
        k_convA_legmix<<<g, 128, 0, s>>>(curA[i], conv_a + i * 1200,
                                         lin_m + i * 720, filt_d,
                                         y1, Lg, lA[i], llA[i], NA, h * HB_);
    };
    auto launchC = [&](int i, int h, cudaStream_t s) {
        int l1 = lA[i] - 2;
        dim3 g((l1 - 2 + 255) / 256, HB_);
        k_conv20b<<<g, 128, 0, s>>>(y1, conv_b + i * 1200, y2, l1, h * HB_);
    };
    auto launchR = [&](int i, int h, cudaStream_t s) {
        dim3 g((loA[i] / 6 + 127) / 128, HB_ * CH_);
        k_recon<<<g, 128, 0, s>>>(Lg, filt_r, y2, curA[i + 1],
                                  llA[i], loA[i], h * HB_);
    };

    // First conv: full batch, main stream
    {
        int l = 16434;
        dim3 g((l + 127) / 128, B_);
        k_first<<<g, 128>>>(input, w_first, xa, l);
    }

    // Stream 0 (main): h0 chain, with skew events after each F
    for (int i = 0; i < NB_; i++) {
        launchF(i, 0, 0);
        cudaEventRecord(evA[i], 0);
        launchC(i, 0, 0);
        launchR(i, 0, 0);
    }
    // Stream 1: h1 chain, each iteration gated on h0's F completion (skew)
    for (int i = 0; i < NB_; i++) {
        cudaStreamWaitEvent(s1, evA[i], 0);
        launchF(i, 1, s1);
        launchC(i, 1, s1);
        launchR(i, 1, s1);
    }
    // Join s1 back into main stream before the full-batch final
    cudaEventRecord(evJ, s1);
    cudaStreamWaitEvent(0, evJ, 0);

    dim3 gfin((LIN_ / 4 + 127) / 128, B_);
    k_final_f2<<<gfin, 128>>>(curA[NB_], w11, w_out, out, lA[NB_ - 1] - 12);
}

// round 16
// speedup vs baseline: 1.4941x; 1.0009x over previous
#include <cuda_runtime.h>
#include <math.h>

#define B_    32
#define HB_   16   // half batch
#define INC_  10
#define LIN_  16384
#define CH_   20
#define NPOLY 12
#define MM_   6
#define NB_   4
// lengths: l0=16434 -> 16422,16410,16398,16386 (all divisible by 6)

#define BUFN 10520000  // >= 32*20*16434

__device__ float g_xa[BUFN];
__device__ float g_xb[BUFN];
__device__ float g_y1[BUFN];
__device__ float g_y2[BUFN];
__device__ float g_lg[BUFN];

typedef unsigned long long ull;

__device__ __forceinline__ ull pk2(float lo, float hi) {
    ull r; asm("mov.b64 %0, {%1, %2};" : "=l"(r) : "f"(lo), "f"(hi)); return r;
}
__device__ __forceinline__ void upk2(ull v, float& lo, float& hi) {
    asm("mov.b64 {%0, %1}, %2;" : "=f"(lo), "=f"(hi) : "l"(v));
}
__device__ __forceinline__ ull fma2(ull a, ull b, ull c) {
    ull d; asm("fma.rn.f32x2 %0, %1, %2, %3;" : "=l"(d) : "l"(a), "l"(b), "l"(c));
    return d;
}

// Branchless gelu: Abramowitz-Stegun 7.1.26 erf approx (|abs err| < 1.5e-7)
__device__ __forceinline__ float gelu_f(float x) {
    float z = 0.7071067811865476f * x;
    float s = fabsf(z);
    float t = __fdividef(1.0f, fmaf(0.3275911f, s, 1.0f));
    float p = fmaf(fmaf(fmaf(fmaf(1.061405429f, t, -1.453152027f),
                             t, 1.421413741f), t, -0.284496736f), t, 0.254829592f) * t;
    float e = __expf(-s * s);
    float er = fmaf(-p, e, 1.0f);
    er = copysignf(er, z);
    return 0.5f * x * (1.0f + er);
}

// ---------------------------------------------------------------------------
// First conv (per-half): wrap-pad (25,27), conv3 10->20.
// ---------------------------------------------------------------------------
__global__ void __launch_bounds__(128) k_first(
    const float* __restrict__ in, const float* __restrict__ w,
    float* __restrict__ out, int lout, int b0)
{
    __shared__ float sw[CH_ * INC_ * 3];
    int tid = threadIdx.x;
    for (int i = tid; i < CH_ * INC_ * 3; i += blockDim.x) sw[i] = w[i];
    __syncthreads();

    int b = b0 + blockIdx.y;
    int t = blockIdx.x * blockDim.x + tid;
    if (t >= lout) return;

    int base = t - 25;
    int i0 = base;     if (i0 < 0) i0 += LIN_; else if (i0 >= LIN_) i0 -= LIN_;
    int i1 = base + 1; if (i1 < 0) i1 += LIN_; else if (i1 >= LIN_) i1 -= LIN_;
    int i2 = base + 2; if (i2 < 0) i2 += LIN_; else if (i2 >= LIN_) i2 -= LIN_;

    const float* inb = in + (size_t)b * INC_ * LIN_;
    float acc[CH_];
#pragma unroll
    for (int co = 0; co < CH_; co++) acc[co] = 0.f;
#pragma unroll
    for (int ci = 0; ci < INC_; ci++) {
        float v0 = inb[ci * LIN_ + i0];
        float v1 = inb[ci * LIN_ + i1];
        float v2 = inb[ci * LIN_ + i2];
#pragma unroll
        for (int co = 0; co < CH_; co++) {
            const float* wp = sw + (co * INC_ + ci) * 3;
            acc[co] = fmaf(wp[0], v0, fmaf(wp[1], v1, fmaf(wp[2], v2, acc[co])));
        }
    }
    float* ob = out + (size_t)b * CH_ * lout;
#pragma unroll
    for (int co = 0; co < CH_; co++) ob[co * lout + t] = acc[co];
}

// ---------------------------------------------------------------------------
// Fused convA(+gelu) ‖ legmix (R9/R14, validated). b0 = batch offset.
// ---------------------------------------------------------------------------
#define TB_ 32
struct SmemConv { float sw[CH_ * CH_ * 3]; };
struct SmemLeg  { float xs[CH_][TB_ * 6 + 6]; float fd2[MM_ * NPOLY]; float lm[CH_ * MM_ * MM_]; };
union SmemU { SmemConv c; SmemLeg l; };

__global__ void __launch_bounds__(128) k_convA_legmix(
    const float* __restrict__ x, const float* __restrict__ wa,
    const float* __restrict__ lm_g, const float* __restrict__ fd,
    float* __restrict__ y1, float* __restrict__ Lg,
    int lin, int ll, int NA, int b0)
{
    __shared__ SmemU smu;
    int tid = threadIdx.x;
    int b = b0 + blockIdx.y;

    if ((int)blockIdx.x < NA) {
        float* sw = smu.c.sw;
        for (int i = tid; i < CH_ * CH_ * 3; i += 128) sw[i] = wa[i];
        __syncthreads();

        int lout = lin - 2;
        int t0 = (blockIdx.x * 128 + tid) * 2;
        if (t0 >= lout) return;
        bool has2 = (t0 + 1 < lout);

        const float* xb = x + (size_t)b * CH_ * lin;
        float a0[CH_], a1[CH_];
#pragma unroll
        for (int co = 0; co < CH_; co++) { a0[co] = 0.f; a1[co] = 0.f; }

#pragma unroll
        for (int ci = 0; ci < CH_; ci++) {
            const float* xp = xb + ci * lin + t0;
            float v0 = xp[0], v1 = xp[1], v2 = xp[2];
            float v3 = has2 ? xp[3] : 0.f;
#pragma unroll
            for (int co = 0; co < CH_; co++) {
                const float* wp = sw + (co * CH_ + ci) * 3;
                float w0 = wp[0], w1 = wp[1], w2 = wp[2];
                a0[co] = fmaf(w0, v0, fmaf(w1, v1, fmaf(w2, v2, a0[co])));
                a1[co] = fmaf(w0, v1, fmaf(w1, v2, fmaf(w2, v3, a1[co])));
            }
        }
        float* ob = y1 + (size_t)b * CH_ * lout;
#pragma unroll
        for (int co = 0; co < CH_; co++) {
            ob[co * lout + t0] = gelu_f(a0[co]);
            if (has2) ob[co * lout + t0 + 1] = gelu_f(a1[co]);
        }
    } else {
        float (*xs)[TB_ * 6 + 6] = smu.l.xs;
        float* fd2 = smu.l.fd2;
        float* lm  = smu.l.lm;

        int T0 = (blockIdx.x - NA) * TB_;

        for (int i = tid; i < MM_ * NPOLY; i += 128) fd2[i] = 0.5f * fd[i];
        for (int i = tid; i < CH_ * MM_ * MM_; i += 128) lm[i] = lm_g[i];
        for (int i = tid; i < CH_ * (TB_ * 6 + 6); i += 128) {
            int ci = i / (TB_ * 6 + 6);
            int j  = i % (TB_ * 6 + 6);
            int pos = 6 * T0 + j;
            xs[ci][j] = (pos < lin) ? x[((size_t)b * CH_ + ci) * lin + pos] : 0.f;
        }
        __syncthreads();

        int wq = tid >> 5, lane = tid & 31;
        int t = T0 + lane;
        if (t >= ll) return;

#pragma unroll
        for (int gg = 0; gg < 5; gg++) {
            int g = wq * 5 + gg;
            float v[MM_];
#pragma unroll
            for (int i = 0; i < MM_; i++) {
                int q  = 6 * g + i;
                int mi = q / CH_;
                int ci = q % CH_;
                float s = 0.f;
#pragma unroll
                for (int k = 0; k < NPOLY; k++)
                    s = fmaf(fd2[mi * NPOLY + k], xs[ci][6 * lane + k], s);
                v[i] = s;
            }
#pragma unroll
            for (int o = 0; o < MM_; o++) {
                float s = 0.f;
#pragma unroll
                for (int i = 0; i < MM_; i++)
                    s = fmaf(lm[(g * MM_ + o) * MM_ + i], v[i], s);
                int p  = 6 * g + o;
                int mo = p / CH_;
                int co = p % CH_;
                Lg[(((size_t)b * MM_ + mo) * CH_ + co) * ll + t] = s;
            }
        }
    }
}

// ---------------------------------------------------------------------------
// conv3 20->20, VALID, no gelu. b0 = batch offset.
// ---------------------------------------------------------------------------
__global__ void __launch_bounds__(128) k_conv20b(
    const float* __restrict__ x, const float* __restrict__ w,
    float* __restrict__ out, int lin, int b0)
{
    __shared__ float sw[CH_ * CH_ * 3];
    int tid = threadIdx.x;
    for (int i = tid; i < CH_ * CH_ * 3; i += blockDim.x) sw[i] = w[i];
    __syncthreads();

    int lout = lin - 2;
    int b = b0 + blockIdx.y;
    int t0 = (blockIdx.x * blockDim.x + tid) * 2;
    if (t0 >= lout) return;
    bool has2 = (t0 + 1 < lout);

    const float* xb = x + (size_t)b * CH_ * lin;
    float a0[CH_], a1[CH_];
#pragma unroll
    for (int co = 0; co < CH_; co++) { a0[co] = 0.f; a1[co] = 0.f; }

#pragma unroll
    for (int ci = 0; ci < CH_; ci++) {
        const float* xp = xb + ci * lin + t0;
        float v0 = xp[0], v1 = xp[1], v2 = xp[2];
        float v3 = has2 ? xp[3] : 0.f;
#pragma unroll
        for (int co = 0; co < CH_; co++) {
            const float* wp = sw + (co * CH_ + ci) * 3;
            float w0 = wp[0], w1 = wp[1], w2 = wp[2];
            a0[co] = fmaf(w0, v0, fmaf(w1, v1, fmaf(w2, v2, a0[co])));
            a1[co] = fmaf(w0, v1, fmaf(w1, v2, fmaf(w2, v3, a1[co])));
        }
    }
    float* ob = out + (size_t)b * CH_ * lout;
#pragma unroll
    for (int co = 0; co < CH_; co++) {
        ob[co * lout + t0] = a0[co];
        if (has2) ob[co * lout + t0 + 1] = a1[co];
    }
}

// ---------------------------------------------------------------------------
// Overlap-add reconstruction + residual + gelu, VT=6. b0 = batch offset.
// blockIdx.y spans HB_*CH_.
// ---------------------------------------------------------------------------
__global__ void __launch_bounds__(128) k_recon(
    const float* __restrict__ Lg, const float* __restrict__ fr,
    const float* __restrict__ y2, float* __restrict__ out,
    int ll, int lout, int b0)
{
    __shared__ float sfr[MM_ * NPOLY];
    __shared__ float sbuf[128 * 6];

    int tid = threadIdx.x;
    if (tid < MM_ * NPOLY) sfr[tid] = fr[tid];
    __syncthreads();

    int bc = b0 * CH_ + blockIdx.y;
    int b = bc / CH_, co = bc % CH_;
    int nu = lout / 6;

    int u = blockIdx.x * 128 + tid;
    if (u < nu) {
        int t0 = u + 1;
        const float* Lo = Lg + (((size_t)b * MM_) * CH_ + co) * ll;
        size_t mstride = (size_t)CH_ * ll;
        float rec[6];
#pragma unroll
        for (int e = 0; e < 6; e++) rec[e] = 0.f;
#pragma unroll
        for (int m = 0; m < MM_; m++) {
            float uc = Lo[m * mstride + t0];
            float up = Lo[m * mstride + t0 - 1];
#pragma unroll
            for (int e = 0; e < 6; e++) {
                rec[e] = fmaf(uc, sfr[m * NPOLY + e],     rec[e]);
                rec[e] = fmaf(up, sfr[m * NPOLY + e + 6], rec[e]);
            }
        }
#pragma unroll
        for (int e = 0; e < 6; e++) sbuf[6 * tid + e] = rec[e];
    }
    __syncthreads();

    int Tbase = blockIdx.x * 768;
    int liny2 = lout + 8;
    const float* y2r = y2 + (size_t)bc * liny2;
    float* outr = out + (size_t)bc * lout;
#pragma unroll
    for (int e2 = 0; e2 < 6; e2++) {
        int idx = tid + 128 * e2;
        int t = Tbase + idx;
        if (t < lout)
            outr[t] = gelu_f(sbuf[idx] + y2r[t + 4]);
    }
}

// ---------------------------------------------------------------------------
// Final 20->128(gelu)->1 with f32x2, VT=4 (per-half).
// ---------------------------------------------------------------------------
__global__ void __launch_bounds__(128) k_final_f2(
    const float* __restrict__ x, const float* __restrict__ w11,
    const float* __restrict__ w_out, float* __restrict__ out, int lin, int b0)
{
    __shared__ __align__(16) float2 swd[128 * CH_];
    __shared__ float so[128];
    int tid = threadIdx.x;
    for (int i = tid; i < 128 * CH_; i += 128) {
        float v = w11[i];
        swd[i] = make_float2(v, v);
    }
    if (tid < 128) so[tid] = w_out[tid];
    __syncthreads();

    int b = b0 + blockIdx.y;
    int t0 = (blockIdx.x * 128 + tid) * 4;
    if (t0 >= LIN_) return;

    const float* xb = x + (size_t)b * CH_ * lin + t0;
    ull xv01[CH_], xv23[CH_];
#pragma unroll
    for (int c = 0; c < CH_; c++) {
        const float* xp = xb + c * lin;
        xv01[c] = pk2(xp[0], xp[1]);
        xv23[c] = pk2(xp[2], xp[3]);
    }

    ull zero = pk2(0.f, 0.f);
    ull acc01 = zero, acc23 = zero;
#pragma unroll 2
    for (int o = 0; o < 128; o++) {
        ull h01 = zero, h23 = zero;
#pragma unroll
        for (int c = 0; c < CH_; c++) {
            ull wv = *(const ull*)&swd[o * CH_ + c];
            h01 = fma2(wv, xv01[c], h01);
            h23 = fma2(wv, xv23[c], h23);
        }
        float h0, h1, h2, h3;
        upk2(h01, h0, h1); upk2(h23, h2, h3);
        float ov = so[o];
        ull ov2 = pk2(ov, ov);
        acc01 = fma2(ov2, pk2(gelu_f(h0), gelu_f(h1)), acc01);
        acc23 = fma2(ov2, pk2(gelu_f(h2), gelu_f(h3)), acc23);
    }
    float r0, r1, r2, r3;
    upk2(acc01, r0, r1); upk2(acc23, r2, r3);
    float4* op = (float4*)&out[(size_t)b * LIN_ + t0];
    *op = make_float4(r0, r1, r2, r3);
}

// ---------------------------------------------------------------------------
extern "C" void kernel_launch(void* const* d_in, const int* in_sizes, int n_in,
                              void* d_out, int out_size)
{
    const float* input  = (const float*)d_in[0];
    const float* w_first= (const float*)d_in[1];
    const float* conv_a = (const float*)d_in[2];
    const float* conv_b = (const float*)d_in[3];
    const float* lin_m  = (const float*)d_in[4];
    const float* w11    = (const float*)d_in[5];
    const float* w_out  = (const float*)d_in[6];
    const float* filt_d = (const float*)d_in[7];
    const float* filt_r = (const float*)d_in[8];
    float* out = (float*)d_out;

    float *xa, *xb, *y1, *y2, *Lg;
    cudaGetSymbolAddress((void**)&xa, g_xa);
    cudaGetSymbolAddress((void**)&xb, g_xb);
    cudaGetSymbolAddress((void**)&y1, g_y1);
    cudaGetSymbolAddress((void**)&y2, g_y2);
    cudaGetSymbolAddress((void**)&Lg, g_lg);

    // Per-iteration lengths and ping-pong buffers
    int lA[NB_], llA[NB_], loA[NB_];
    float* curA[NB_ + 1];
    curA[0] = xa;
    {
        int l = 16434;
        for (int i = 0; i < NB_; i++) {
            lA[i] = l; llA[i] = l / 6 - 1; loA[i] = l - 12;
            curA[i + 1] = (i % 2 == 0) ? xb : xa;
            l -= 12;
        }
    }

    // Fork-join resources — SAME footprint as R14 (1 stream, 7 events),
    // which is empirically capture-safe on this harness.
    cudaStream_t s1;
    cudaStreamCreateWithFlags(&s1, cudaStreamNonBlocking);
    cudaEvent_t evRoot, evA[NB_], evJ;
    cudaEventCreateWithFlags(&evRoot, cudaEventDisableTiming);
    for (int i = 0; i < NB_; i++)
        cudaEventCreateWithFlags(&evA[i], cudaEventDisableTiming);
    cudaEventCreateWithFlags(&evJ, cudaEventDisableTiming);

    auto launchFirst = [&](int h, cudaStream_t s) {
        dim3 g((16434 + 127) / 128, HB_);
        k_first<<<g, 128, 0, s>>>(input, w_first, xa, 16434, h * HB_);
    };
    auto launchF = [&](int i, int h, cudaStream_t s) {
        int NA = (lA[i] - 2 + 255) / 256;
        int NL = (llA[i] + TB_ - 1) / TB_;
        dim3 g(NA + NL, HB_);
        k_convA_legmix<<<g, 128, 0, s>>>(curA[i], conv_a + i * 1200,
                                         lin_m + i * 720, filt_d,
                                         y1, Lg, lA[i], llA[i], NA, h * HB_);
    };
    auto launchC = [&](int i, int h, cudaStream_t s) {
        int l1 = lA[i] - 2;
        dim3 g((l1 - 2 + 255) / 256, HB_);
        k_conv20b<<<g, 128, 0, s>>>(y1, conv_b + i * 1200, y2, l1, h * HB_);
    };
    auto launchR = [&](int i, int h, cudaStream_t s) {
        dim3 g((loA[i] / 6 + 127) / 128, HB_ * CH_);
        k_recon<<<g, 128, 0, s>>>(Lg, filt_r, y2, curA[i + 1],
                                  llA[i], loA[i], h * HB_);
    };
    auto launchFinal = [&](int h, cudaStream_t s) {
        dim3 g((LIN_ / 4 + 127) / 128, HB_);
        k_final_f2<<<g, 128, 0, s>>>(curA[NB_], w11, w_out, out,
                                     loA[NB_ - 1], h * HB_);
    };

    // Fork: root event on capture-origin stream, s1 joins before its work.
    cudaEventRecord(evRoot, 0);

    // Stream 0: h0 chain (first -> 4x{F,C,R} -> final), skew events after F.
    launchFirst(0, 0);
    for (int i = 0; i < NB_; i++) {
        launchF(i, 0, 0);
        cudaEventRecord(evA[i], 0);
        launchC(i, 0, 0);
        launchR(i, 0, 0);
    }
    launchFinal(0, 0);

    // Stream 1: h1 chain, gated per-iter on h0's F event (one-stage skew).
    cudaStreamWaitEvent(s1, evRoot, 0);
    launchFirst(1, s1);
    for (int i = 0; i < NB_; i++) {
        cudaStreamWaitEvent(s1, evA[i], 0);
        launchF(i, 1, s1);
        launchC(i, 1, s1);
        launchR(i, 1, s1);
    }
    launchFinal(1, s1);

    // Join s1 back into the capture-origin stream.
    cudaEventRecord(evJ, s1);
    cudaStreamWaitEvent(0, evJ, 0);
}